// round 16
// baseline (speedup 1.0000x reference)
#include <cuda_runtime.h>
#include <cuda_bf16.h>
#include <cstdint>

// Dims
#define T 64
#define B 8
#define H 128
#define NH 4
#define D 256
#define HB (NH*B)          // 32
#define EPS 1e-5f
#define INV_SQRT_D 0.0625f
#define KSPLIT 16

typedef unsigned long long u64;

// ---- packed f32x2 helpers (SASS FFMA2) --------------------------------------
__device__ __forceinline__ u64 bcast2(float x) {
    u64 r; asm("mov.b64 %0, {%1,%1};" : "=l"(r) : "f"(x)); return r;
}
__device__ __forceinline__ void ffma2(u64& d, u64 a, u64 b) {
    asm("fma.rn.f32x2 %0, %1, %2, %3;" : "=l"(d) : "l"(a), "l"(b), "l"(d));
}
__device__ __forceinline__ float2 unpack2(u64 v) {
    float x, y; asm("mov.b64 {%0,%1}, %2;" : "=f"(x), "=f"(y) : "l"(v));
    return make_float2(x, y);
}

// ---------------- scratch (device globals; no allocation) ----------------
__device__ float g_xin [T*B*D];
__device__ float g_trig[T*B*D];
__device__ float g_qk  [T*NH*B*D];
__device__ float g_ipre[T*HB];
__device__ float g_fpre[T*HB];
__device__ float g_ad  [T*HB];
__device__ float g_bd  [T*HB];
__device__ float g_q [NH*B*T*D];     // [hb][t][e]
__device__ float g_k [NH*B*T*D];
__device__ float g_v [NH*B*T*D];
__device__ float g_og[NH*B*T*D];
__device__ float g_sk[NH*B*T*D];
__device__ float g_h [T*NH*B*D];     // [t][h][b][d]
__device__ float g_hn[T*B*NH*D];     // BN2'd, [(t*B+b)][h*D+d]
__device__ float g_pp[KSPLIT*T*B*D]; // poll partials [kz][(t*B+b)][e]

// ---------------- K1b: BN1 (inline) + up-proj GEMM [512,128]x[128,512] -------
__global__ __launch_bounds__(256) void k1b(const float* __restrict__ x,
                                           const float* __restrict__ bn1_s,
                                           const float* __restrict__ bn1_b,
                                           const float* __restrict__ Wup1,
                                           const float* __restrict__ bup1,
                                           const float* __restrict__ Wup2,
                                           const float* __restrict__ bup2)
{
    int tm = blockIdx.x;   // 0..7
    int tn = blockIdx.y;   // 0..7

    __shared__ float As[32*68];  // k-major As[c*68 + r]
    __shared__ float Bs[32*68];

    int tid = threadIdx.x;
    int tx = tid & 15;
    int ty = tid >> 4;

    u64 acc2[2][4];
    #pragma unroll
    for (int i = 0; i < 2; i++)
        #pragma unroll
        for (int j = 0; j < 4; j++) acc2[i][j] = 0ull;

    for (int kt = 0; kt < 4; kt++) {
        #pragma unroll
        for (int i = 0; i < 8; i++) {
            int e = tid + 256*i;
            int r = e >> 5, c = e & 31;
            As[c*68 + r] = x[(tm*64 + r)*H + kt*32 + c];
        }
        #pragma unroll
        for (int i = 0; i < 8; i++) {
            int e = tid + 256*i;
            int kr = e >> 6, cc = e & 63;
            int jrow = kt*32 + kr;
            int col = tn*64 + cc;
            float w = (col < 256) ? Wup1[jrow*D + col] : Wup2[jrow*D + col - 256];
            Bs[kr*68 + cc] = w;
        }
        __syncthreads();

        // BN1 inline
        {
            int tl = tid >> 5;
            int c  = tid & 31;
            float* base = &As[c*68 + tl*8];
            float s = 0.f, s2 = 0.f;
            #pragma unroll
            for (int bb = 0; bb < 8; bb++) { float v = base[bb]; s += v; s2 += v*v; }
            float mu  = s * 0.125f;
            float var = s2 * 0.125f - mu*mu;
            float inv = rsqrtf(var + EPS);
            int j = kt*32 + c;
            float sc = bn1_s[j]*inv, ofs = bn1_b[j];
            #pragma unroll
            for (int bb = 0; bb < 8; bb++) base[bb] = (base[bb] - mu)*sc + ofs;
        }
        __syncthreads();

        #pragma unroll
        for (int kk = 0; kk < 32; kk++) {
            const u64* ap2 = (const u64*)&As[kk*68 + ty*4];
            u64 ap[2] = {ap2[0], ap2[1]};
            float4 b4 = *(const float4*)&Bs[kk*68 + tx*4];
            u64 bb[4] = {bcast2(b4.x), bcast2(b4.y), bcast2(b4.z), bcast2(b4.w)};
            #pragma unroll
            for (int i = 0; i < 2; i++)
                #pragma unroll
                for (int j = 0; j < 4; j++) ffma2(acc2[i][j], ap[i], bb[j]);
        }
        __syncthreads();
    }

    bool istrig = (tn >= 4);
    #pragma unroll
    for (int ip = 0; ip < 2; ip++) {
        #pragma unroll
        for (int half = 0; half < 2; half++) {
            int row = tm*64 + ty*4 + ip*2 + half;
            int col = tn*64 + tx*4;
            float rv[4];
            #pragma unroll
            for (int j = 0; j < 4; j++) {
                float2 p = unpack2(acc2[ip][j]);
                rv[j] = half ? p.y : p.x;
            }
            if (!istrig) {
                float4 o;
                o.x = rv[0] + bup1[col+0];
                o.y = rv[1] + bup1[col+1];
                o.z = rv[2] + bup1[col+2];
                o.w = rv[3] + bup1[col+3];
                *(float4*)&g_xin[(size_t)row*D + col] = o;
            } else {
                int c2 = col - 256;
                float4 o; float tv;
                tv = rv[0] + bup2[c2+0]; o.x = tv / (1.f + expf(-tv));
                tv = rv[1] + bup2[c2+1]; o.y = tv / (1.f + expf(-tv));
                tv = rv[2] + bup2[c2+2]; o.z = tv / (1.f + expf(-tv));
                tv = rv[3] + bup2[c2+3]; o.w = tv / (1.f + expf(-tv));
                *(float4*)&g_trig[(size_t)row*D + c2] = o;
            }
        }
    }
}

// ---------------- K1c: conv/qk + gate pre-acts -------------------------------
__global__ __launch_bounds__(256) void k1c(const float* __restrict__ convk,
                                           const float* __restrict__ convb,
                                           const float* __restrict__ Wi,
                                           const float* __restrict__ bi,
                                           const float* __restrict__ Wf,
                                           const float* __restrict__ bf)
{
    int t = blockIdx.x;
    int tid = threadIdx.x;
    __shared__ float xins[B*D];

    for (int i = tid; i < B*D; i += 256) xins[i] = g_xin[(size_t)t*B*D + i];
    __syncthreads();

    for (int idx = tid; idx < NH*B*D; idx += 256) {
        int hh = idx / (B*D);
        int rem = idx % (B*D);
        int bb = rem / D, dd = rem % D;
        float acc = convb[hh];
        #pragma unroll
        for (int w = 0; w < 4; w++) {
            int dj = dd - 1 + w;
            if (dj >= 0 && dj < D) acc = fmaf(xins[bb*D + dj], convk[w*NH + hh], acc);
        }
        g_qk[((t*NH + hh)*B + bb)*D + dd] = acc / (1.f + expf(-acc));
    }

    {
        int g = tid >> 2;
        int r = tid & 3;
        int which = g >> 5;
        int p = g & 31;
        int hh = p >> 3, bb = p & 7;
        const float* W = which ? (Wf + hh*D) : (Wi + hh*D);
        const float* xb = xins + bb*D;
        float acc = 0.f;
        for (int u = 0; u < 64; u++) {
            int dd = r + 4*u;
            acc = fmaf(xb[dd], W[dd], acc);
        }
        acc += __shfl_xor_sync(0xffffffffu, acc, 1);
        acc += __shfl_xor_sync(0xffffffffu, acc, 2);
        if (r == 0) {
            if (which) g_fpre[t*HB + p] = acc + bf[hh];
            else       g_ipre[t*HB + p] = acc + bi[hh];
        }
    }
}

// ---------------- K2: warp-parallel gate scan --------------------------------
__global__ __launch_bounds__(1024) void k2_scan()
{
    __shared__ float si[T*33];
    __shared__ float sf[T*33];
    int tid = threadIdx.x;

    for (int i = tid; i < T*HB; i += 1024) {
        int t = i >> 5, p = i & 31;
        si[t*33 + p] = g_ipre[i];
        sf[t*33 + p] = g_fpre[i];
    }
    __syncthreads();

    int p = tid >> 5;
    int l = tid & 31;
    int t0 = 2*l, t1 = 2*l + 1;
    float f0 = sf[t0*33 + p], f1 = sf[t1*33 + p];
    float i0 = si[t0*33 + p], i1 = si[t1*33 + p];

    float ps = f0 + f1;
    float s = ps;
    #pragma unroll
    for (int d = 1; d < 32; d <<= 1) {
        float o = __shfl_up_sync(0xffffffffu, s, d);
        if (l >= d) s += o;
    }
    float excl = s - ps;
    float cf0 = excl + f0;
    float cf1 = excl + ps;

    float F = f0 + f1;
    float I = fmaxf(i0 + f1, i1);
    #pragma unroll
    for (int d = 1; d < 32; d <<= 1) {
        float Fo = __shfl_up_sync(0xffffffffu, F, d);
        float Io = __shfl_up_sync(0xffffffffu, I, d);
        if (l >= d) {
            I = fmaxf(Io + F, I);
            F = Fo + F;
        }
    }
    float m1 = fmaxf(F, I);
    float Fe = __shfl_up_sync(0xffffffffu, F, 1);
    float Ie = __shfl_up_sync(0xffffffffu, I, 1);
    if (l == 0) { Fe = 0.f; Ie = -3.0e38f; }
    float m0v = fmaxf(Fe + f0, fmaxf(Ie + f0, i0));

    g_ad[t0*HB + p] = i0 - cf0;
    g_ad[t1*HB + p] = i1 - cf1;
    g_bd[t0*HB + p] = cf0 - m0v;
    g_bd[t1*HB + p] = cf1 - m1;
}

// ---------------- K3: batched projection GEMMs (128x128 tiles, 8x8/thread) ---
// grid (8, 20): bx&3 = M tile (128 rows), bx>>2 = N tile (128 cols)
__global__ __launch_bounds__(256) void k3_gemm(
    const float* __restrict__ Wq, const float* __restrict__ bq,
    const float* __restrict__ Wk, const float* __restrict__ bk,
    const float* __restrict__ Wv, const float* __restrict__ bv,
    const float* __restrict__ Wo, const float* __restrict__ bo,
    const float* __restrict__ Wsk,const float* __restrict__ bsk)
{
    int inst = blockIdx.y;           // 0..19
    int proj = inst / NH;
    int h    = inst % NH;
    int tm = blockIdx.x & 3;         // 4 M tiles of 128
    int tn = blockIdx.x >> 2;        // 2 N tiles of 128

    const float* W; const float* bias; int src;
    switch (proj) {
        case 0: W = Wq;  bias = bq;  src = 0; break;
        case 1: W = Wk;  bias = bk;  src = 0; break;
        case 2: W = Wv;  bias = bv;  src = 1; break;
        case 3: W = Wo;  bias = bo;  src = 1; break;
        default:W = Wsk; bias = bsk; src = 0; break;
    }

    __shared__ float As[32*132];  // k-major As[c*132 + r], r<128
    __shared__ float Bs[32*132];  // Bs[kr*132 + cc], cc<128

    int tid = threadIdx.x;
    int tx = tid & 15;
    int ty = tid >> 4;

    u64 acc2[4][8];   // [row-pair][col]
    #pragma unroll
    for (int i = 0; i < 4; i++)
        #pragma unroll
        for (int j = 0; j < 8; j++) acc2[i][j] = 0ull;

    const float* Wb = W + (size_t)h*D*D;

    for (int kt = 0; kt < 8; kt++) {
        // A: 128x32 tile, LDG.128 + k-major scatter
        #pragma unroll
        for (int i = 0; i < 4; i++) {
            int v = tid + 256*i;       // 0..1023
            int r = v >> 3;            // 0..127
            int c4 = v & 7;
            int gr = tm*128 + r;
            int t = gr >> 3, bb = gr & 7;
            const float* srcp = (src == 0)
                ? &g_qk[((t*NH + h)*B + bb)*D + kt*32 + c4*4]
                : &g_xin[(t*B + bb)*D + kt*32 + c4*4];
            float4 av = *(const float4*)srcp;
            As[(c4*4+0)*132 + r] = av.x;
            As[(c4*4+1)*132 + r] = av.y;
            As[(c4*4+2)*132 + r] = av.z;
            As[(c4*4+3)*132 + r] = av.w;
        }
        // B: 32x128 tile, vectorized
        #pragma unroll
        for (int i = 0; i < 4; i++) {
            int v = tid + 256*i;       // 0..1023
            int kr = v >> 5;           // 0..31
            int c4 = v & 31;
            *(float4*)&Bs[kr*132 + c4*4] =
                *(const float4*)&Wb[(kt*32 + kr)*D + tn*128 + c4*4];
        }
        __syncthreads();
        #pragma unroll
        for (int kk = 0; kk < 32; kk++) {
            const u64* ap2 = (const u64*)&As[kk*132 + ty*8];
            u64 ap[4] = {ap2[0], ap2[1], ap2[2], ap2[3]};
            float4 b0 = *(const float4*)&Bs[kk*132 + tx*8];
            float4 b1 = *(const float4*)&Bs[kk*132 + tx*8 + 4];
            float bcols[8] = {b0.x, b0.y, b0.z, b0.w, b1.x, b1.y, b1.z, b1.w};
            #pragma unroll
            for (int j = 0; j < 8; j++) {
                u64 bj = bcast2(bcols[j]);
                #pragma unroll
                for (int i = 0; i < 4; i++) ffma2(acc2[i][j], ap[i], bj);
            }
        }
        __syncthreads();
    }

    #pragma unroll
    for (int ip = 0; ip < 4; ip++) {
        #pragma unroll
        for (int half = 0; half < 2; half++) {
            int gr = tm*128 + ty*8 + ip*2 + half;
            int t = gr >> 3, bb = gr & 7;
            float rv[8];
            #pragma unroll
            for (int j = 0; j < 8; j++) {
                float2 pr = unpack2(acc2[ip][j]);
                rv[j] = half ? pr.y : pr.x;
            }
            size_t obase = ((size_t)(h*B + bb)*T + t)*D;
            #pragma unroll
            for (int q = 0; q < 2; q++) {
                int e0 = tn*128 + tx*8 + q*4;
                float vv[4];
                #pragma unroll
                for (int jj = 0; jj < 4; jj++)
                    vv[jj] = rv[q*4 + jj] + bias[h*D + e0 + jj];
                float4 o;
                if (proj == 0) {
                    o = make_float4(vv[0], vv[1], vv[2], vv[3]);
                    *(float4*)&g_q[obase + e0] = o;
                } else if (proj == 1) {
                    o = make_float4(vv[0]*INV_SQRT_D, vv[1]*INV_SQRT_D,
                                    vv[2]*INV_SQRT_D, vv[3]*INV_SQRT_D);
                    *(float4*)&g_k[obase + e0] = o;
                } else if (proj == 2) {
                    o = make_float4(vv[0], vv[1], vv[2], vv[3]);
                    *(float4*)&g_v[obase + e0] = o;
                } else if (proj == 3) {
                    o.x = 1.f / (1.f + expf(-vv[0]));
                    o.y = 1.f / (1.f + expf(-vv[1]));
                    o.z = 1.f / (1.f + expf(-vv[2]));
                    o.w = 1.f / (1.f + expf(-vv[3]));
                    *(float4*)&g_og[obase + e0] = o;
                } else {
                    o = make_float4(vv[0], vv[1], vv[2], vv[3]);
                    *(float4*)&g_sk[obase + e0] = o;
                }
            }
        }
    }
}

// ---------------- K4: fused S=QK^T + decay/mask/rowsum + O=W.V ---------------
// grid (HB, 2): block recomputes full S (in regs), outputs e-slice [y*128..)
__global__ __launch_bounds__(256) void k4()
{
    __shared__ float WsT[64*68];    // phase2: Q-chunk [c<32][r<64]; phase3+: W^T [s][t]
    __shared__ float Ks [32*68];    // phase2: K-chunk
    __shared__ float Vs [64*132];   // phase3+: V [s][el<128]
    __shared__ float ad_s[64];
    __shared__ float bd_s[64];
    __shared__ float sc_s[64];

    int hb = blockIdx.x;
    int h = hb >> 3, b = hb & 7;
    int eoff = blockIdx.y * 128;
    int tid = threadIdx.x;
    int tx = tid & 15;
    int ty = tid >> 4;

    if (tid < 64) {
        ad_s[tid] = g_ad[tid*HB + hb];
        bd_s[tid] = g_bd[tid*HB + hb];
    }

    const float* Qg = g_q + (size_t)hb*T*D;
    const float* Kg = g_k + (size_t)hb*T*D;

    u64 acc2[2][4];
    #pragma unroll
    for (int i = 0; i < 2; i++)
        #pragma unroll
        for (int j = 0; j < 4; j++) acc2[i][j] = 0ull;

    // phase 2: S = Q.K^T over 256 e in 8 chunks of 32 (thread tile 4x4)
    for (int ch = 0; ch < 8; ch++) {
        #pragma unroll
        for (int i = 0; i < 2; i++) {
            int v = tid + 256*i;      // 0..511
            int r = v >> 3;           // 0..63
            int c4 = v & 7;
            float4 qv = *(const float4*)&Qg[r*D + ch*32 + c4*4];
            float4 kv = *(const float4*)&Kg[r*D + ch*32 + c4*4];
            WsT[(c4*4+0)*68 + r] = qv.x;
            WsT[(c4*4+1)*68 + r] = qv.y;
            WsT[(c4*4+2)*68 + r] = qv.z;
            WsT[(c4*4+3)*68 + r] = qv.w;
            Ks [(c4*4+0)*68 + r] = kv.x;
            Ks [(c4*4+1)*68 + r] = kv.y;
            Ks [(c4*4+2)*68 + r] = kv.z;
            Ks [(c4*4+3)*68 + r] = kv.w;
        }
        __syncthreads();
        #pragma unroll
        for (int kk = 0; kk < 32; kk++) {
            const u64* ap2 = (const u64*)&WsT[kk*68 + ty*4];
            u64 ap[2] = {ap2[0], ap2[1]};
            float4 b4 = *(const float4*)&Ks[kk*68 + tx*4];
            u64 bb[4] = {bcast2(b4.x), bcast2(b4.y), bcast2(b4.z), bcast2(b4.w)};
            #pragma unroll
            for (int i = 0; i < 2; i++)
                #pragma unroll
                for (int j = 0; j < 4; j++) ffma2(acc2[i][j], ap[i], bb[j]);
        }
        __syncthreads();
    }

    // phase 3: decay/mask into WsT (transposed), load V slice
    float wreg[4][4];
    #pragma unroll
    for (int ip = 0; ip < 2; ip++) {
        #pragma unroll
        for (int half = 0; half < 2; half++) {
            int t = ty*4 + ip*2 + half;
            float bdv = bd_s[t];
            #pragma unroll
            for (int j = 0; j < 4; j++) {
                int s = tx*4 + j;
                float2 pr = unpack2(acc2[ip][j]);
                float val = half ? pr.y : pr.x;
                wreg[ip*2 + half][j] = (s <= t) ? expf(ad_s[s] + bdv) * val : 0.f;
            }
        }
    }
    __syncthreads();   // done reading Q-chunk region before overwrite
    #pragma unroll
    for (int i = 0; i < 4; i++) {
        int t = ty*4 + i;
        #pragma unroll
        for (int j = 0; j < 4; j++)
            WsT[(tx*4 + j)*68 + t] = wreg[i][j];
    }
    const float* Vg = g_v + (size_t)hb*T*D;
    #pragma unroll
    for (int i = 0; i < 8; i++) {
        int v = tid + 256*i;          // 0..2047
        int s = v >> 5, e4 = v & 31;
        *(float4*)&Vs[s*132 + e4*4] =
            *(const float4*)&Vg[s*D + eoff + e4*4];
    }
    __syncthreads();

    // phase 4: rowsum -> scaler
    if (tid < 64) {
        float r = 0.f;
        #pragma unroll 8
        for (int s = 0; s < 64; s++) r += WsT[s*68 + tid];
        sc_s[tid] = 1.f / fmaxf(fabsf(r), 1.f);
    }
    __syncthreads();

    // phase 5: O = W.V  (thread tile 4t x 8e; B-paired FFMA2)
    u64 oacc[4][4];   // [t_i][e_pair]
    #pragma unroll
    for (int i = 0; i < 4; i++)
        #pragma unroll
        for (int j = 0; j < 4; j++) oacc[i][j] = 0ull;

    #pragma unroll 4
    for (int s = 0; s < 64; s++) {
        float4 w4 = *(const float4*)&WsT[s*68 + ty*4];
        const u64* bp = (const u64*)&Vs[s*132 + tx*8];
        u64 bb[4] = {bp[0], bp[1], bp[2], bp[3]};
        u64 aw[4] = {bcast2(w4.x), bcast2(w4.y), bcast2(w4.z), bcast2(w4.w)};
        #pragma unroll
        for (int i = 0; i < 4; i++)
            #pragma unroll
            for (int j = 0; j < 4; j++) ffma2(oacc[i][j], aw[i], bb[j]);
    }

    const float* OGg = g_og + (size_t)hb*T*D;
    const float* SKg = g_sk + (size_t)hb*T*D;
    #pragma unroll
    for (int i = 0; i < 4; i++) {
        int t = ty*4 + i;
        float scv = sc_s[t];
        float av[8];
        #pragma unroll
        for (int j = 0; j < 4; j++) {
            float2 pr = unpack2(oacc[i][j]);
            av[2*j] = pr.x; av[2*j+1] = pr.y;
        }
        #pragma unroll
        for (int q = 0; q < 2; q++) {
            int ecol = eoff + tx*8 + q*4;
            float4 og4 = *(const float4*)&OGg[t*D + ecol];
            float4 sk4 = *(const float4*)&SKg[t*D + ecol];
            float4 hv;
            hv.x = og4.x * av[q*4+0] * scv + sk4.x;
            hv.y = og4.y * av[q*4+1] * scv + sk4.y;
            hv.z = og4.z * av[q*4+2] * scv + sk4.z;
            hv.w = og4.w * av[q*4+3] * scv + sk4.w;
            *(float4*)&g_h[((size_t)(t*NH + h)*B + b)*D + ecol] = hv;
        }
    }
}

// ---------------- K5a: BN2 + re-layout ---------------------------------------
__global__ __launch_bounds__(256) void k5a(const float* __restrict__ bn2_s,
                                           const float* __restrict__ bn2_b)
{
    int t = blockIdx.x;
    int tid = threadIdx.x;
    __shared__ float hs[32*257];

    for (int i = tid; i < 32*256; i += 256) {
        int p = i >> 8, d = i & 255;
        hs[p*257 + d] = g_h[(size_t)t*NH*B*D + p*256 + d];
    }
    __syncthreads();

    int d = tid;
    float s = 0.f, s2 = 0.f;
    #pragma unroll
    for (int p = 0; p < 32; p++) { float v = hs[p*257 + d]; s += v; s2 += v*v; }
    float mu  = s * (1.f/32);
    float var = s2 * (1.f/32) - mu*mu;
    float inv = rsqrtf(var + EPS);
    float sc = bn2_s[d]*inv, ofs = bn2_b[d];
    #pragma unroll
    for (int p = 0; p < 32; p++) {
        int hh = p >> 3, bb = p & 7;
        g_hn[(size_t)(t*B + bb)*(NH*D) + hh*D + d] = (hs[p*257 + d] - mu)*sc + ofs;
    }
}

// ---------------- K5b: poll GEMM, 128x128 tiles, K-split 16 ------------------
// grid (4, 2, 16): M tile, N tile, kz (K=64 each)
__global__ __launch_bounds__(256) void k5b(const float* __restrict__ Wpoll)
{
    int tm = blockIdx.x;   // 0..3 (128-row tiles)
    int tn = blockIdx.y;   // 0..1 (128-col tiles)
    int kz = blockIdx.z;   // 0..15

    __shared__ float As[32*132];
    __shared__ float Bs[32*132];

    int tid = threadIdx.x;
    int tx = tid & 15;
    int ty = tid >> 4;

    u64 acc2[4][8];
    #pragma unroll
    for (int i = 0; i < 4; i++)
        #pragma unroll
        for (int j = 0; j < 8; j++) acc2[i][j] = 0ull;

    for (int kt = 0; kt < 2; kt++) {
        int k0 = kz*64 + kt*32;
        #pragma unroll
        for (int i = 0; i < 4; i++) {
            int v = tid + 256*i;      // 0..1023
            int r = v >> 3;           // 0..127
            int c4 = v & 7;
            float4 av = *(const float4*)&g_hn[(size_t)(tm*128 + r)*(NH*D) + k0 + c4*4];
            As[(c4*4+0)*132 + r] = av.x;
            As[(c4*4+1)*132 + r] = av.y;
            As[(c4*4+2)*132 + r] = av.z;
            As[(c4*4+3)*132 + r] = av.w;
        }
        #pragma unroll
        for (int i = 0; i < 4; i++) {
            int v = tid + 256*i;
            int kr = v >> 5, c4 = v & 31;
            *(float4*)&Bs[kr*132 + c4*4] =
                *(const float4*)&Wpoll[(size_t)(k0 + kr)*D + tn*128 + c4*4];
        }
        __syncthreads();
        #pragma unroll
        for (int kk = 0; kk < 32; kk++) {
            const u64* ap2 = (const u64*)&As[kk*132 + ty*8];
            u64 ap[4] = {ap2[0], ap2[1], ap2[2], ap2[3]};
            float4 b0 = *(const float4*)&Bs[kk*132 + tx*8];
            float4 b1 = *(const float4*)&Bs[kk*132 + tx*8 + 4];
            float bcols[8] = {b0.x, b0.y, b0.z, b0.w, b1.x, b1.y, b1.z, b1.w};
            #pragma unroll
            for (int j = 0; j < 8; j++) {
                u64 bj = bcast2(bcols[j]);
                #pragma unroll
                for (int i = 0; i < 4; i++) ffma2(acc2[i][j], ap[i], bj);
            }
        }
        __syncthreads();
    }

    #pragma unroll
    for (int ip = 0; ip < 4; ip++) {
        #pragma unroll
        for (int half = 0; half < 2; half++) {
            int row = tm*128 + ty*8 + ip*2 + half;
            float rv[8];
            #pragma unroll
            for (int j = 0; j < 8; j++) {
                float2 pr = unpack2(acc2[ip][j]);
                rv[j] = half ? pr.y : pr.x;
            }
            #pragma unroll
            for (int q = 0; q < 2; q++) {
                *(float4*)&g_pp[(size_t)kz*T*B*D + (size_t)row*D + tn*128 + tx*8 + q*4] =
                    make_float4(rv[q*4+0], rv[q*4+1], rv[q*4+2], rv[q*4+3]);
            }
        }
    }
}

// ---------------- K5c: combine partials + trig gate + down + residual --------
__global__ __launch_bounds__(256) void k5c(
    const float* __restrict__ x,
    const float* __restrict__ bpoll,
    const float* __restrict__ Wdown, const float* __restrict__ bdown,
    float* __restrict__ out)
{
    int t = blockIdx.x;
    int tid = threadIdx.x;
    __shared__ float ps[B*D];

    for (int i = tid; i < B*D; i += 256) {
        int bb = i >> 8, e = i & 255;
        size_t row = (size_t)(t*B + bb)*D + e;
        float pv = bpoll[e];
        #pragma unroll
        for (int z = 0; z < KSPLIT; z++)
            pv += g_pp[(size_t)z*T*B*D + row];
        ps[bb*D + e] = pv * g_trig[row];
    }
    __syncthreads();

    int j = tid & 127;
    int bg = tid >> 7;
    float acc[4] = {0.f, 0.f, 0.f, 0.f};
    for (int e = 0; e < D; e++) {
        float w = Wdown[e*H + j];
        #pragma unroll
        for (int q = 0; q < 4; q++) acc[q] = fmaf(ps[(bg*4 + q)*D + e], w, acc[q]);
    }
    #pragma unroll
    for (int q = 0; q < 4; q++) {
        int bb = bg*4 + q;
        out[(t*B + bb)*H + j] = acc[q] + bdown[j] + x[(t*B + bb)*H + j];
    }
}

// ---------------- launch -----------------------------------------------------
extern "C" void kernel_launch(void* const* d_in, const int* in_sizes, int n_in,
                              void* d_out, int out_size)
{
    const float* x      = (const float*)d_in[0];
    const float* Wq     = (const float*)d_in[1];
    const float* bq     = (const float*)d_in[2];
    const float* Wk     = (const float*)d_in[3];
    const float* bk     = (const float*)d_in[4];
    const float* Wv     = (const float*)d_in[5];
    const float* bv     = (const float*)d_in[6];
    const float* convk  = (const float*)d_in[7];
    const float* convb  = (const float*)d_in[8];
    const float* Wi     = (const float*)d_in[9];
    const float* bi     = (const float*)d_in[10];
    const float* Wf     = (const float*)d_in[11];
    const float* bf     = (const float*)d_in[12];
    const float* Wo     = (const float*)d_in[13];
    const float* bo     = (const float*)d_in[14];
    const float* Wsk    = (const float*)d_in[15];
    const float* bsk    = (const float*)d_in[16];
    const float* bn1_s  = (const float*)d_in[17];
    const float* bn1_b  = (const float*)d_in[18];
    const float* bn2_s  = (const float*)d_in[19];
    const float* bn2_b  = (const float*)d_in[20];
    const float* Wup1   = (const float*)d_in[21];
    const float* bup1   = (const float*)d_in[22];
    const float* Wup2   = (const float*)d_in[23];
    const float* bup2   = (const float*)d_in[24];
    const float* Wpoll  = (const float*)d_in[25];
    const float* bpoll  = (const float*)d_in[26];
    const float* Wdown  = (const float*)d_in[27];
    const float* bdown  = (const float*)d_in[28];
    float* out = (float*)d_out;

    k1b<<<dim3(8, 8), 256>>>(x, bn1_s, bn1_b, Wup1, bup1, Wup2, bup2);
    k1c<<<T, 256>>>(convk, convb, Wi, bi, Wf, bf);
    k2_scan<<<1, 1024>>>();
    k3_gemm<<<dim3(8, 20), 256>>>(Wq, bq, Wk, bk, Wv, bv, Wo, bo, Wsk, bsk);
    k4<<<dim3(HB, 2), 256>>>();
    k5a<<<T, 256>>>(bn2_s, bn2_b);
    k5b<<<dim3(4, 2, KSPLIT), 256>>>(Wpoll);
    k5c<<<T, 256>>>(x, bpoll, Wdown, bdown, out);
}